// round 15
// baseline (speedup 1.0000x reference)
#include <cuda_runtime.h>
#include <cstdint>

namespace {
constexpr int Bsz    = 16384;
constexpr int Ncap   = 32;
constexpr int Din    = 128;
constexpr int Dout   = 256;
constexpr int RITERS = 3;

constexpr int A_STRIDE = 144;            // conflict-free LDS.128 (group = 4*row+qc mod 8)
constexpr int A_WK     = 32 * A_STRIDE;  // 4608 floats per worker (one batch)

// shared memory layout (float offsets)
constexpr int OFF_W    = 0;                  // 32768 floats (W fragments, tf32, k-permuted)
constexpr int OFF_A    = OFF_W + 32768;      // 4 workers * A_WK
constexpr int OFF_BIAS = OFF_A + 4 * A_WK;   // 256
constexpr int OFF_SCR  = OFF_BIAS + 256;     // per-worker scratch
// scratch offsets within a worker
constexpr int S_NRM  = 0;      // [32][4] = 128
constexpr int S_BIJ0 = 128;    // 32
constexpr int S_BIJ1 = 160;    // 32
constexpr int S_SQP0 = 192;    // 4
constexpr int S_SQP1 = 196;    // 4
constexpr int S_AGR0 = 200;    // [32][4] = 128
constexpr int S_AGR1 = 328;    // 128
constexpr int SCR_SIZE = 464;
constexpr int SMEM_FLOATS = OFF_SCR + 4 * SCR_SIZE;
constexpr int SMEM_BYTES  = SMEM_FLOATS * 4;   // ~212 KB
}

__device__ __forceinline__ float to_tf32(float x) {
    float y;
    asm("cvt.rna.tf32.f32 %0, %1;" : "=f"(y) : "f"(x));
    return y;
}

__device__ __forceinline__ void bar_wk(int wk) {
    asm volatile("bar.sync %0, 128;" :: "r"(1 + wk) : "memory");
}

__device__ __forceinline__ void cp_async16(uint32_t saddr, const void* gptr) {
    asm volatile("cp.async.cg.shared.global [%0], [%1], 16;\n"
                 :: "r"(saddr), "l"(gptr));
}
__device__ __forceinline__ void cp_commit() {
    asm volatile("cp.async.commit_group;\n" ::: "memory");
}
__device__ __forceinline__ void cp_wait0() {
    asm volatile("cp.async.wait_group 0;\n" ::: "memory");
}

// ---- packed f32x2 helpers (sm_103a FFMA2 path) ----
__device__ __forceinline__ uint64_t pk(float lo, float hi) {
    uint64_t r;
    asm("mov.b64 %0, {%1, %2};" : "=l"(r) : "f"(lo), "f"(hi));
    return r;
}
__device__ __forceinline__ void upk(uint64_t v, float& lo, float& hi) {
    asm("mov.b64 {%0, %1}, %2;" : "=f"(lo), "=f"(hi) : "l"(v));
}
__device__ __forceinline__ uint64_t f2fma(uint64_t a, uint64_t b, uint64_t c) {
    uint64_t d;
    asm("fma.rn.f32x2 %0, %1, %2, %3;" : "=l"(d) : "l"(a), "l"(b), "l"(c));
    return d;
}
__device__ __forceinline__ uint64_t f2mul(uint64_t a, uint64_t b) {
    uint64_t d;
    asm("mul.rn.f32x2 %0, %1, %2;" : "=l"(d) : "l"(a), "l"(b));
    return d;
}
__device__ __forceinline__ uint64_t f2add(uint64_t a, uint64_t b) {
    uint64_t d;
    asm("add.rn.f32x2 %0, %1, %2;" : "=l"(d) : "l"(a), "l"(b));
    return d;
}
__device__ __forceinline__ uint64_t shfl64(uint64_t v, int off) {
    return (uint64_t)__shfl_xor_sync(0xffffffffu, (unsigned long long)v, off);
}

// A operand registers carry raw fp32 bits; tf32 MMA reads bits[31:13] (RZ).
__device__ __forceinline__ void mma_tf32(float* c, float a0, float a1, float a2, float a3,
                                         float b0, float b1) {
    asm volatile(
        "mma.sync.aligned.m16n8k8.row.col.f32.tf32.tf32.f32 "
        "{%0,%1,%2,%3}, {%4,%5,%6,%7}, {%8,%9}, {%0,%1,%2,%3};\n"
        : "+f"(c[0]), "+f"(c[1]), "+f"(c[2]), "+f"(c[3])
        : "r"(__float_as_uint(a0)), "r"(__float_as_uint(a1)),
          "r"(__float_as_uint(a2)), "r"(__float_as_uint(a3)),
          "r"(__float_as_uint(b0)), "r"(__float_as_uint(b1)));
}

__global__ void __launch_bounds__(512, 1)
dyr_agg_kernel(const float* __restrict__ embeds,
               const float* __restrict__ weights,
               const float* __restrict__ Wg,
               const float* __restrict__ bg,
               float* __restrict__ out)
{
    extern __shared__ float sm[];
    const int tid  = threadIdx.x;
    const int wk   = tid >> 7;       // 0..3: independent 128-thread worker (one batch)
    const int wtid = tid & 127;
    const int lane = tid & 31;
    const int cg   = (tid >> 5) & 3; // warp-in-worker = column group (64 cols at cg*64)
    const int qr   = lane >> 2;      // 0..7
    const int qc   = lane & 3;       // 0..3

    float* scr = sm + OFF_SCR + wk * SCR_SIZE;
    float* As  = sm + OFF_A + wk * A_WK;
    const uint32_t As_u32  = (uint32_t)__cvta_generic_to_shared(As);
    const uint32_t scr_u32 = (uint32_t)__cvta_generic_to_shared(scr);

    // ---- issue async copy of this worker's FIRST batch (overlaps W staging) ----
    int b0i = blockIdx.x * 4 + wk;
    if (b0i < Bsz) {
        const float4* eg = (const float4*)(embeds + (size_t)b0i * Ncap * Din);
        #pragma unroll
        for (int t = 0; t < 8; t++) {
            int i   = wtid + t * 128;       // 1024 float4s (32 rows x 32)
            int row = i >> 5, j4 = i & 31;
            cp_async16(As_u32 + (row * A_STRIDE + j4 * 4) * 4, eg + i);
        }
        if (wtid < 8)   // 32 floats of routing logits -> slot 0
            cp_async16(scr_u32 + (S_BIJ0 + wtid * 4) * 4,
                       weights + (size_t)b0i * Ncap + wtid * 4);
    }
    cp_commit();

    // ---- stage W (paired-j, k16-group-permuted layout) + bias, whole CTA, once ----
    // MMA step s = 2t + r uses phys k rows: logical (ln&3) -> 16t + 4*(ln&3) + 2r,
    // logical (ln&3)+4 -> +1. Matches the A-side float4 pair-compressed loads.
    for (int idx = tid; idx < 16 * 16 * 32; idx += 512) {
        int nt2 = idx >> 9;
        int s   = (idx >> 5) & 15;
        int ln  = idx & 31;
        int p0  = (s >> 1) * 16 + 4 * (ln & 3) + 2 * (s & 1);
        int n0  = nt2 * 16 + (ln >> 2);
        sm[OFF_W + idx * 4 + 0] = to_tf32(Wg[p0 * Dout + n0]);
        sm[OFF_W + idx * 4 + 1] = to_tf32(Wg[(p0 + 1) * Dout + n0]);
        sm[OFF_W + idx * 4 + 2] = to_tf32(Wg[p0 * Dout + n0 + 8]);
        sm[OFF_W + idx * 4 + 3] = to_tf32(Wg[(p0 + 1) * Dout + n0 + 8]);
    }
    if (tid < Dout) sm[OFF_BIAS + tid] = bg[tid];
    __syncthreads();

    float* out_poses = out;
    float* out_c     = out + (size_t)Bsz * Dout;

    const int stride = gridDim.x * 4;
    int p = 0;  // b_ij slot parity (per loop iteration)
    for (int b = b0i; b < Bsz; b += stride, p ^= 1) {
        const int  nb       = b + stride;
        const bool has_next = nb < Bsz;
        const int  BIJ      = p ? S_BIJ1 : S_BIJ0;
        const int  BIJN     = p ? S_BIJ0 : S_BIJ1;

        // A + b_ij for this batch were issued last iteration (or prologue)
        cp_wait0();
        bar_wk(wk);   // [bar 1]

        // routing logits, register-resident (lane = capsule index n)
        float bij = scr[BIJ + lane];

        // ---- GEMM: each warp computes 32 rows x 64 cols (cg) ----
        float c[2][8][4];
        #pragma unroll
        for (int mt = 0; mt < 2; mt++)
            #pragma unroll
            for (int j = 0; j < 8; j++)
                #pragma unroll
                for (int q = 0; q < 4; q++) c[mt][j][q] = 0.0f;

        #pragma unroll
        for (int t = 0; t < 8; t++) {
            // One float4 per (mt,row-half) feeds MMA steps 2t and 2t+1.
            float4 f0[2], f1[2];
            #pragma unroll
            for (int mt = 0; mt < 2; mt++) {
                const float* ar = As + (mt * 16) * A_STRIDE + t * 16 + 4 * qc;
                f0[mt] = *(const float4*)&ar[qr * A_STRIDE];
                f1[mt] = *(const float4*)&ar[(qr + 8) * A_STRIDE];
            }
            #pragma unroll
            for (int r = 0; r < 2; r++) {
                int s = 2 * t + r;
                #pragma unroll
                for (int jp = 0; jp < 4; jp++) {
                    float4 b4 = *(const float4*)&sm[OFF_W + (((cg * 4 + jp) * 16 + s) * 32 + lane) * 4];
                    #pragma unroll
                    for (int mt = 0; mt < 2; mt++) {
                        float a0 = r ? f0[mt].z : f0[mt].x;
                        float a1 = r ? f1[mt].z : f1[mt].x;
                        float a2 = r ? f0[mt].w : f0[mt].y;
                        float a3 = r ? f1[mt].w : f1[mt].y;
                        mma_tf32(c[mt][2 * jp + 0], a0, a1, a2, a3, b4.x, b4.y);
                        mma_tf32(c[mt][2 * jp + 1], a0, a1, a2, a3, b4.z, b4.w);
                    }
                }
            }
        }

        // ---- bias add + per-row squared-norm partials, PACKED f32x2 ----
        // cc[mt][j][h] packs cols (qc*2, qc*2+1) of row (mt*16 + qr + h*8), col group j.
        // cc stays UNNORMALIZED (x); inv is folded into the routing coefficients.
        uint64_t cc[2][8][2];
        uint64_t pn2[2][2] = {{0ull, 0ull}, {0ull, 0ull}};
        #pragma unroll
        for (int j = 0; j < 8; j++) {
            uint64_t b2 = *(const uint64_t*)&sm[OFF_BIAS + cg * 64 + j * 8 + qc * 2];
            #pragma unroll
            for (int mt = 0; mt < 2; mt++)
                #pragma unroll
                for (int h = 0; h < 2; h++) {
                    uint64_t v2 = f2add(pk(c[mt][j][2 * h], c[mt][j][2 * h + 1]), b2);
                    pn2[mt][h] = f2fma(v2, v2, pn2[mt][h]);
                    cc[mt][j][h] = v2;
                }
        }
        #pragma unroll
        for (int mt = 0; mt < 2; mt++)
            #pragma unroll
            for (int h = 0; h < 2; h++) {
                float lo, hi; upk(pn2[mt][h], lo, hi);
                float v = lo + hi;
                v += __shfl_xor_sync(0xffffffffu, v, 1);
                v += __shfl_xor_sync(0xffffffffu, v, 2);
                if (qc == 0) {
                    int n = mt * 16 + qr + h * 8;
                    scr[S_NRM + n * 4 + cg] = v;
                }
            }
        bar_wk(wk);   // [bar 2] GEMM reads of A done; norm partials visible

        // ---- A buffer now dead: issue next batch's async copies (overlap routing) ----
        if (has_next) {
            const float4* eg = (const float4*)(embeds + (size_t)nb * Ncap * Din);
            #pragma unroll
            for (int t = 0; t < 8; t++) {
                int i   = wtid + t * 128;
                int row = i >> 5, j4 = i & 31;
                cp_async16(As_u32 + (row * A_STRIDE + j4 * 4) * 4, eg + i);
            }
            if (wtid < 8)
                cp_async16(scr_u32 + (BIJN + wtid * 4) * 4,
                           weights + (size_t)nb * Ncap + wtid * 4);
        }
        cp_commit();

        // inv-norm for THIS lane's capsule (n = lane); folded into coefficients
        float inv_lane;
        {
            float4 nr = *(const float4*)&scr[S_NRM + lane * 4];
            inv_lane = rsqrtf(fmaxf(nr.x + nr.y + nr.z + nr.w, 1e-24f));
        }

        // ---- dynamic routing: ONE barrier per iteration, packed math ----
        float cval = 0.0f;
        #pragma unroll 1
        for (int it = 0; it < RITERS; it++) {
            const int SQP = (it & 1) ? S_SQP1 : S_SQP0;
            const int AGR = (it & 1) ? S_AGR1 : S_AGR0;

            // softmax over capsules (no max-shift: |b_ij| bounded ~6.5, fp32-safe)
            float e = __expf(bij);
            float ssum = e;
            #pragma unroll
            for (int off = 16; off; off >>= 1)
                ssum += __shfl_xor_sync(0xffffffffu, ssum, off);
            cval = e * (32.0f / ssum);
            float ci = cval * inv_lane;   // c_n * inv_n : gives true s from x

            float cv0 = __shfl_sync(0xffffffffu, ci, qr);
            float cv1 = __shfl_sync(0xffffffffu, ci, qr + 8);
            float cv2 = __shfl_sync(0xffffffffu, ci, qr + 16);
            float cv3 = __shfl_sync(0xffffffffu, ci, qr + 24);
            uint64_t cv0_2 = pk(cv0, cv0), cv1_2 = pk(cv1, cv1);
            uint64_t cv2_2 = pk(cv2, cv2), cv3_2 = pk(cv3, cv3);

            // s[d] = sum_n (c_n inv_n) x[n][d], packed pairs
            uint64_t sp2[8];
            #pragma unroll
            for (int j = 0; j < 8; j++) {
                uint64_t v = f2mul(cv0_2, cc[0][j][0]);
                v = f2fma(cv1_2, cc[0][j][1], v);
                v = f2fma(cv2_2, cc[1][j][0], v);
                v = f2fma(cv3_2, cc[1][j][1], v);
                sp2[j] = v;
            }
            #pragma unroll
            for (int j = 0; j < 8; j++) {
                sp2[j] = f2add(sp2[j], shfl64(sp2[j], 4));
                sp2[j] = f2add(sp2[j], shfl64(sp2[j], 8));
                sp2[j] = f2add(sp2[j], shfl64(sp2[j], 16));
            }

            // warp-partial sum(s^2) over this warp's 64 cols
            uint64_t qs2 = 0ull;
            #pragma unroll
            for (int j = 0; j < 8; j++)
                qs2 = f2fma(sp2[j], sp2[j], qs2);
            float ql, qh; upk(qs2, ql, qh);
            float qs = ql + qh;
            qs += __shfl_xor_sync(0xffffffffu, qs, 1);
            qs += __shfl_xor_sync(0xffffffffu, qs, 2);
            if (lane == 0) scr[SQP + cg] = qs;

            if (it < RITERS - 1) {
                // UNSCALED x·s partials (inv_n and scale applied at the update)
                uint64_t ap2[2][2] = {{0ull, 0ull}, {0ull, 0ull}};
                #pragma unroll
                for (int j = 0; j < 8; j++) {
                    ap2[0][0] = f2fma(cc[0][j][0], sp2[j], ap2[0][0]);
                    ap2[0][1] = f2fma(cc[0][j][1], sp2[j], ap2[0][1]);
                    ap2[1][0] = f2fma(cc[1][j][0], sp2[j], ap2[1][0]);
                    ap2[1][1] = f2fma(cc[1][j][1], sp2[j], ap2[1][1]);
                }
                #pragma unroll
                for (int mt = 0; mt < 2; mt++)
                    #pragma unroll
                    for (int h = 0; h < 2; h++) {
                        float lo, hi; upk(ap2[mt][h], lo, hi);
                        float a = lo + hi;
                        a += __shfl_xor_sync(0xffffffffu, a, 1);
                        a += __shfl_xor_sync(0xffffffffu, a, 2);
                        if (qc == 0) {
                            int n = mt * 16 + qr + h * 8;
                            scr[AGR + n * 4 + cg] = a;
                        }
                    }
            }
            bar_wk(wk);   // [one bar per iteration]

            float4 q4 = *(const float4*)&scr[SQP];
            float t4 = q4.x + q4.y + q4.z + q4.w;
            float scale = t4 / ((1.0f + t4) * sqrtf(t4 + 1e-9f));

            if (it < RITERS - 1) {
                // agree_n = inv_n * (x_n . s); every warp updates its register b_ij
                float4 ag = *(const float4*)&scr[AGR + lane * 4];
                bij += (scale * inv_lane) * (ag.x + ag.y + ag.z + ag.w);
            } else {
                // final iter: v straight from registers to GMEM (no smem staging)
                uint64_t sc2 = pk(scale, scale);
                float* op = out_poses + (size_t)b * Dout + cg * 64 + qc * 2;
                #pragma unroll
                for (int j = 0; j < 8; j++)
                    if (qr == j)
                        *(uint64_t*)(op + j * 8) = f2mul(sp2[j], sc2);
                if (cg == 0)
                    out_c[(size_t)b * Ncap + lane] = cval;
            }
        }
        // no trailing barrier: next unit's bar1/bar2 order all remaining
        // smem hazards (S_NRM, SQP/AGR parity verified across units).
    }
}

extern "C" void kernel_launch(void* const* d_in, const int* in_sizes, int n_in,
                              void* d_out, int out_size) {
    const float* embeds  = (const float*)d_in[0];
    const float* weights = (const float*)d_in[1];
    const float* Wg      = (const float*)d_in[2];
    const float* bg      = (const float*)d_in[3];
    float* out = (float*)d_out;

    cudaFuncSetAttribute(dyr_agg_kernel,
                         cudaFuncAttributeMaxDynamicSharedMemorySize, SMEM_BYTES);
    int sms = 148;
    cudaDeviceGetAttribute(&sms, cudaDevAttrMultiProcessorCount, 0);
    dyr_agg_kernel<<<sms, 512, SMEM_BYTES>>>(embeds, weights, Wg, bg, out);
}

// round 16
// speedup vs baseline: 1.0861x; 1.0861x over previous
#include <cuda_runtime.h>
#include <cstdint>

namespace {
constexpr int Bsz    = 16384;
constexpr int Ncap   = 32;
constexpr int Din    = 128;
constexpr int Dout   = 256;
constexpr int RITERS = 3;

constexpr int A_STRIDE = 136;            // conflict-free LDS.64 (phase-bijective)
constexpr int A_WK     = 32 * A_STRIDE;  // 4352 floats per worker (one batch)

// shared memory layout (float offsets)
constexpr int OFF_W    = 0;                  // 32768 floats (W fragments, tf32, k-permuted)
constexpr int OFF_A    = OFF_W + 32768;      // 4 workers * A_WK
constexpr int OFF_BIAS = OFF_A + 4 * A_WK;   // 256
constexpr int OFF_SCR  = OFF_BIAS + 256;     // per-worker scratch
// scratch offsets within a worker
constexpr int S_NRM  = 0;      // [32][4] = 128
constexpr int S_BIJ0 = 128;    // 32
constexpr int S_BIJ1 = 160;    // 32
constexpr int S_SQP0 = 192;    // 4
constexpr int S_SQP1 = 196;    // 4
constexpr int S_AGR0 = 200;    // [32][4] = 128
constexpr int S_AGR1 = 328;    // 128
constexpr int SCR_SIZE = 464;
constexpr int SMEM_FLOATS = OFF_SCR + 4 * SCR_SIZE;
constexpr int SMEM_BYTES  = SMEM_FLOATS * 4;   // ~208 KB

constexpr long long STAGGER_CYC = 2800;   // ~1/4 unit period per worker rank
}

__device__ __forceinline__ float to_tf32(float x) {
    float y;
    asm("cvt.rna.tf32.f32 %0, %1;" : "=f"(y) : "f"(x));
    return y;
}

__device__ __forceinline__ void bar_wk(int wk) {
    asm volatile("bar.sync %0, 128;" :: "r"(1 + wk) : "memory");
}

__device__ __forceinline__ void cp_async16(uint32_t saddr, const void* gptr) {
    asm volatile("cp.async.cg.shared.global [%0], [%1], 16;\n"
                 :: "r"(saddr), "l"(gptr));
}
__device__ __forceinline__ void cp_commit() {
    asm volatile("cp.async.commit_group;\n" ::: "memory");
}
__device__ __forceinline__ void cp_wait0() {
    asm volatile("cp.async.wait_group 0;\n" ::: "memory");
}

// ---- packed f32x2 helpers (sm_103a FFMA2 path) ----
__device__ __forceinline__ uint64_t pk(float lo, float hi) {
    uint64_t r;
    asm("mov.b64 %0, {%1, %2};" : "=l"(r) : "f"(lo), "f"(hi));
    return r;
}
__device__ __forceinline__ void upk(uint64_t v, float& lo, float& hi) {
    asm("mov.b64 {%0, %1}, %2;" : "=f"(lo), "=f"(hi) : "l"(v));
}
__device__ __forceinline__ uint64_t f2fma(uint64_t a, uint64_t b, uint64_t c) {
    uint64_t d;
    asm("fma.rn.f32x2 %0, %1, %2, %3;" : "=l"(d) : "l"(a), "l"(b), "l"(c));
    return d;
}
__device__ __forceinline__ uint64_t f2mul(uint64_t a, uint64_t b) {
    uint64_t d;
    asm("mul.rn.f32x2 %0, %1, %2;" : "=l"(d) : "l"(a), "l"(b));
    return d;
}
__device__ __forceinline__ uint64_t f2add(uint64_t a, uint64_t b) {
    uint64_t d;
    asm("add.rn.f32x2 %0, %1, %2;" : "=l"(d) : "l"(a), "l"(b));
    return d;
}
__device__ __forceinline__ uint64_t shfl64(uint64_t v, int off) {
    return (uint64_t)__shfl_xor_sync(0xffffffffu, (unsigned long long)v, off);
}

// A operand registers carry raw fp32 bits; tf32 MMA reads bits[31:13] (RZ).
__device__ __forceinline__ void mma_tf32(float* c, const float* a, float b0, float b1) {
    asm volatile(
        "mma.sync.aligned.m16n8k8.row.col.f32.tf32.tf32.f32 "
        "{%0,%1,%2,%3}, {%4,%5,%6,%7}, {%8,%9}, {%0,%1,%2,%3};\n"
        : "+f"(c[0]), "+f"(c[1]), "+f"(c[2]), "+f"(c[3])
        : "r"(__float_as_uint(a[0])), "r"(__float_as_uint(a[1])),
          "r"(__float_as_uint(a[2])), "r"(__float_as_uint(a[3])),
          "r"(__float_as_uint(b0)), "r"(__float_as_uint(b1)));
}

__global__ void __launch_bounds__(512, 1)
dyr_agg_kernel(const float* __restrict__ embeds,
               const float* __restrict__ weights,
               const float* __restrict__ Wg,
               const float* __restrict__ bg,
               float* __restrict__ out)
{
    extern __shared__ float sm[];
    const int tid  = threadIdx.x;
    const int wk   = tid >> 7;       // 0..3: independent 128-thread worker (one batch)
    const int wtid = tid & 127;
    const int lane = tid & 31;
    const int cg   = (tid >> 5) & 3; // warp-in-worker = column group (64 cols at cg*64)
    const int qr   = lane >> 2;      // 0..7
    const int qc   = lane & 3;       // 0..3

    float* scr = sm + OFF_SCR + wk * SCR_SIZE;
    float* As  = sm + OFF_A + wk * A_WK;
    const uint32_t As_u32  = (uint32_t)__cvta_generic_to_shared(As);
    const uint32_t scr_u32 = (uint32_t)__cvta_generic_to_shared(scr);

    // ---- issue async copy of this worker's FIRST batch (overlaps W staging) ----
    int b0i = blockIdx.x * 4 + wk;
    if (b0i < Bsz) {
        const float4* eg = (const float4*)(embeds + (size_t)b0i * Ncap * Din);
        #pragma unroll
        for (int t = 0; t < 8; t++) {
            int i   = wtid + t * 128;       // 1024 float4s (32 rows x 32)
            int row = i >> 5, j4 = i & 31;
            cp_async16(As_u32 + (row * A_STRIDE + j4 * 4) * 4, eg + i);
        }
        if (wtid < 8)   // 32 floats of routing logits -> slot 0
            cp_async16(scr_u32 + (S_BIJ0 + wtid * 4) * 4,
                       weights + (size_t)b0i * Ncap + wtid * 4);
    }
    cp_commit();

    // ---- stage W (paired-j, k-permuted layout) + bias, whole CTA, once ----
    for (int idx = tid; idx < 16 * 16 * 32; idx += 512) {
        int nt2 = idx >> 9;
        int ks  = (idx >> 5) & 15;
        int ln  = idx & 31;
        int p0  = ks * 8 + 2 * (ln & 3);
        int n0  = nt2 * 16 + (ln >> 2);
        sm[OFF_W + idx * 4 + 0] = to_tf32(Wg[p0 * Dout + n0]);
        sm[OFF_W + idx * 4 + 1] = to_tf32(Wg[(p0 + 1) * Dout + n0]);
        sm[OFF_W + idx * 4 + 2] = to_tf32(Wg[p0 * Dout + n0 + 8]);
        sm[OFF_W + idx * 4 + 3] = to_tf32(Wg[(p0 + 1) * Dout + n0 + 8]);
    }
    if (tid < Dout) sm[OFF_BIAS + tid] = bg[tid];
    __syncthreads();

    // ---- deterministic worker phase-stagger: desynchronize the 4 workers so
    // GEMM bursts (tensor+LDS) of one overlap routing bursts (shfl+bar) of the
    // others on the shared SMSPs. One-time cost <= 3*STAGGER_CYC.
    if (wk > 0) {
        long long t0 = clock64();
        while (clock64() - t0 < (long long)wk * STAGGER_CYC) { }
    }

    float* out_poses = out;
    float* out_c     = out + (size_t)Bsz * Dout;

    const int stride = gridDim.x * 4;
    int p = 0;  // b_ij slot parity (per loop iteration)
    for (int b = b0i; b < Bsz; b += stride, p ^= 1) {
        const int  nb       = b + stride;
        const bool has_next = nb < Bsz;
        const int  BIJ      = p ? S_BIJ1 : S_BIJ0;
        const int  BIJN     = p ? S_BIJ0 : S_BIJ1;

        // A + b_ij for this batch were issued last iteration (or prologue)
        cp_wait0();
        bar_wk(wk);   // [bar 1]

        // routing logits, register-resident (lane = capsule index n)
        float bij = scr[BIJ + lane];

        // ---- GEMM: each warp computes 32 rows x 64 cols (cg) ----
        float c[2][8][4];
        #pragma unroll
        for (int mt = 0; mt < 2; mt++)
            #pragma unroll
            for (int j = 0; j < 8; j++)
                #pragma unroll
                for (int q = 0; q < 4; q++) c[mt][j][q] = 0.0f;

        #pragma unroll
        for (int ks = 0; ks < 16; ks++) {
            float a[2][4];
            #pragma unroll
            for (int mt = 0; mt < 2; mt++) {
                const float* ar = As + (mt * 16) * A_STRIDE + ks * 8 + 2 * qc;
                float2 f0 = *(const float2*)&ar[qr * A_STRIDE];
                float2 f1 = *(const float2*)&ar[(qr + 8) * A_STRIDE];
                a[mt][0] = f0.x; a[mt][1] = f1.x;   // logical col qc
                a[mt][2] = f0.y; a[mt][3] = f1.y;   // logical col qc+4
            }
            #pragma unroll
            for (int jp = 0; jp < 4; jp++) {
                float4 b4 = *(const float4*)&sm[OFF_W + (((cg * 4 + jp) * 16 + ks) * 32 + lane) * 4];
                mma_tf32(c[0][2 * jp + 0], a[0], b4.x, b4.y);
                mma_tf32(c[1][2 * jp + 0], a[1], b4.x, b4.y);
                mma_tf32(c[0][2 * jp + 1], a[0], b4.z, b4.w);
                mma_tf32(c[1][2 * jp + 1], a[1], b4.z, b4.w);
            }
        }

        // ---- bias add + per-row squared-norm partials, PACKED f32x2 ----
        // cc[mt][j][h] packs cols (qc*2, qc*2+1) of row (mt*16 + qr + h*8), col group j.
        // cc stays UNNORMALIZED (x); inv is folded into the routing coefficients.
        uint64_t cc[2][8][2];
        uint64_t pn2[2][2] = {{0ull, 0ull}, {0ull, 0ull}};
        #pragma unroll
        for (int j = 0; j < 8; j++) {
            uint64_t b2 = *(const uint64_t*)&sm[OFF_BIAS + cg * 64 + j * 8 + qc * 2];
            #pragma unroll
            for (int mt = 0; mt < 2; mt++)
                #pragma unroll
                for (int h = 0; h < 2; h++) {
                    uint64_t v2 = f2add(pk(c[mt][j][2 * h], c[mt][j][2 * h + 1]), b2);
                    pn2[mt][h] = f2fma(v2, v2, pn2[mt][h]);
                    cc[mt][j][h] = v2;
                }
        }
        #pragma unroll
        for (int mt = 0; mt < 2; mt++)
            #pragma unroll
            for (int h = 0; h < 2; h++) {
                float lo, hi; upk(pn2[mt][h], lo, hi);
                float v = lo + hi;
                v += __shfl_xor_sync(0xffffffffu, v, 1);
                v += __shfl_xor_sync(0xffffffffu, v, 2);
                if (qc == 0) {
                    int n = mt * 16 + qr + h * 8;
                    scr[S_NRM + n * 4 + cg] = v;
                }
            }
        bar_wk(wk);   // [bar 2] GEMM reads of A done; norm partials visible

        // ---- A buffer now dead: issue next batch's async copies (overlap routing) ----
        if (has_next) {
            const float4* eg = (const float4*)(embeds + (size_t)nb * Ncap * Din);
            #pragma unroll
            for (int t = 0; t < 8; t++) {
                int i   = wtid + t * 128;
                int row = i >> 5, j4 = i & 31;
                cp_async16(As_u32 + (row * A_STRIDE + j4 * 4) * 4, eg + i);
            }
            if (wtid < 8)
                cp_async16(scr_u32 + (BIJN + wtid * 4) * 4,
                           weights + (size_t)nb * Ncap + wtid * 4);
        }
        cp_commit();

        // inv-norm for THIS lane's capsule (n = lane); folded into coefficients
        float inv_lane;
        {
            float4 nr = *(const float4*)&scr[S_NRM + lane * 4];
            inv_lane = rsqrtf(fmaxf(nr.x + nr.y + nr.z + nr.w, 1e-24f));
        }

        // ---- dynamic routing: ONE barrier per iteration, packed math ----
        float cval = 0.0f;
        #pragma unroll 1
        for (int it = 0; it < RITERS; it++) {
            const int SQP = (it & 1) ? S_SQP1 : S_SQP0;
            const int AGR = (it & 1) ? S_AGR1 : S_AGR0;

            // softmax over capsules (no max-shift: |b_ij| bounded ~6.5, fp32-safe)
            float e = __expf(bij);
            float ssum = e;
            #pragma unroll
            for (int off = 16; off; off >>= 1)
                ssum += __shfl_xor_sync(0xffffffffu, ssum, off);
            cval = e * (32.0f / ssum);
            float ci = cval * inv_lane;   // c_n * inv_n : gives true s from x

            float cv0 = __shfl_sync(0xffffffffu, ci, qr);
            float cv1 = __shfl_sync(0xffffffffu, ci, qr + 8);
            float cv2 = __shfl_sync(0xffffffffu, ci, qr + 16);
            float cv3 = __shfl_sync(0xffffffffu, ci, qr + 24);
            uint64_t cv0_2 = pk(cv0, cv0), cv1_2 = pk(cv1, cv1);
            uint64_t cv2_2 = pk(cv2, cv2), cv3_2 = pk(cv3, cv3);

            // s[d] = sum_n (c_n inv_n) x[n][d], packed pairs
            uint64_t sp2[8];
            #pragma unroll
            for (int j = 0; j < 8; j++) {
                uint64_t v = f2mul(cv0_2, cc[0][j][0]);
                v = f2fma(cv1_2, cc[0][j][1], v);
                v = f2fma(cv2_2, cc[1][j][0], v);
                v = f2fma(cv3_2, cc[1][j][1], v);
                sp2[j] = v;
            }
            #pragma unroll
            for (int j = 0; j < 8; j++) {
                sp2[j] = f2add(sp2[j], shfl64(sp2[j], 4));
                sp2[j] = f2add(sp2[j], shfl64(sp2[j], 8));
                sp2[j] = f2add(sp2[j], shfl64(sp2[j], 16));
            }

            // warp-partial sum(s^2) over this warp's 64 cols
            uint64_t qs2 = 0ull;
            #pragma unroll
            for (int j = 0; j < 8; j++)
                qs2 = f2fma(sp2[j], sp2[j], qs2);
            float ql, qh; upk(qs2, ql, qh);
            float qs = ql + qh;
            qs += __shfl_xor_sync(0xffffffffu, qs, 1);
            qs += __shfl_xor_sync(0xffffffffu, qs, 2);
            if (lane == 0) scr[SQP + cg] = qs;

            if (it < RITERS - 1) {
                // UNSCALED x·s partials (inv_n and scale applied at the update)
                uint64_t ap2[2][2] = {{0ull, 0ull}, {0ull, 0ull}};
                #pragma unroll
                for (int j = 0; j < 8; j++) {
                    ap2[0][0] = f2fma(cc[0][j][0], sp2[j], ap2[0][0]);
                    ap2[0][1] = f2fma(cc[0][j][1], sp2[j], ap2[0][1]);
                    ap2[1][0] = f2fma(cc[1][j][0], sp2[j], ap2[1][0]);
                    ap2[1][1] = f2fma(cc[1][j][1], sp2[j], ap2[1][1]);
                }
                #pragma unroll
                for (int mt = 0; mt < 2; mt++)
                    #pragma unroll
                    for (int h = 0; h < 2; h++) {
                        float lo, hi; upk(ap2[mt][h], lo, hi);
                        float a = lo + hi;
                        a += __shfl_xor_sync(0xffffffffu, a, 1);
                        a += __shfl_xor_sync(0xffffffffu, a, 2);
                        if (qc == 0) {
                            int n = mt * 16 + qr + h * 8;
                            scr[AGR + n * 4 + cg] = a;
                        }
                    }
            }
            bar_wk(wk);   // [one bar per iteration]

            float4 q4 = *(const float4*)&scr[SQP];
            float t4 = q4.x + q4.y + q4.z + q4.w;
            float scale = t4 / ((1.0f + t4) * sqrtf(t4 + 1e-9f));

            if (it < RITERS - 1) {
                // agree_n = inv_n * (x_n . s); every warp updates its register b_ij
                float4 ag = *(const float4*)&scr[AGR + lane * 4];
                bij += (scale * inv_lane) * (ag.x + ag.y + ag.z + ag.w);
            } else {
                // final iter: v straight from registers to GMEM (no smem staging)
                uint64_t sc2 = pk(scale, scale);
                float* op = out_poses + (size_t)b * Dout + cg * 64 + qc * 2;
                #pragma unroll
                for (int j = 0; j < 8; j++)
                    if (qr == j)
                        *(uint64_t*)(op + j * 8) = f2mul(sp2[j], sc2);
                if (cg == 0)
                    out_c[(size_t)b * Ncap + lane] = cval;
            }
        }
        // no trailing barrier: next unit's bar1/bar2 order all remaining
        // smem hazards (S_NRM, SQP/AGR parity verified across units).
    }
}

extern "C" void kernel_launch(void* const* d_in, const int* in_sizes, int n_in,
                              void* d_out, int out_size) {
    const float* embeds  = (const float*)d_in[0];
    const float* weights = (const float*)d_in[1];
    const float* Wg      = (const float*)d_in[2];
    const float* bg      = (const float*)d_in[3];
    float* out = (float*)d_out;

    cudaFuncSetAttribute(dyr_agg_kernel,
                         cudaFuncAttributeMaxDynamicSharedMemorySize, SMEM_BYTES);
    int sms = 148;
    cudaDeviceGetAttribute(&sms, cudaDevAttrMultiProcessorCount, 0);
    dyr_agg_kernel<<<sms, 512, SMEM_BYTES>>>(embeds, weights, Wg, bg, out);
}